// round 16
// baseline (speedup 1.0000x reference)
#include <cuda_runtime.h>
#include <math.h>
#include <stdio.h>
#include <assert.h>

#define Vv 30000
#define Ee 300
#define Hd 300
#define G4 1200
#define Td 9
#define Bd 256
#define Sd 256

// ---- scratch (device globals) ----
__device__ float  g_table_f[(size_t)Vv * G4];
__device__ float  g_table_b[(size_t)Vv * G4];
__device__ float  g_hf[(size_t)Sd * Hd * Bd];   // [time][h][b]
__device__ float  g_hb[(size_t)Sd * Hd * Bd];
__device__ float  g_cf[Hd * Bd];                // [h][b]
__device__ float  g_cb[Hd * Bd];
__device__ double g_em[(size_t)Sd * Bd * Td];
__device__ unsigned char g_bp[(size_t)(Sd - 1) * Bd * Td];

__device__ __forceinline__ float clampg(float v) {
    return fmaxf(fminf(v, 30.f), -30.f);
}

// f32x2 packed fma: d = a*b + d (two independent fp32 FMAs, exact rounding)
__device__ __forceinline__ void fma2(unsigned long long& d,
                                     unsigned long long a, unsigned long long b) {
    asm("fma.rn.f32x2 %0, %1, %2, %0;" : "+l"(d) : "l"(a), "l"(b));
}
__device__ __forceinline__ float2 u2f(unsigned long long v) {
    float2 r;
    asm("mov.b64 {%0, %1}, %2;" : "=f"(r.x), "=f"(r.y) : "l"(v));
    return r;
}

struct SizePack { int n; int v[16]; };
__global__ void bad_layout_kernel(SizePack sp)
{
    printf("[diag] LAYOUT MISMATCH n_in=%d sizes:", sp.n);
    for (int i = 0; i < 16 && i < sp.n; i++) printf(" %d", sp.v[i]);
    printf("\n");
    assert(0);
}

// ============================================================
// Phase 1: vocab gate table (128x128 tile, 8x8 micro, f32x2).
// (identical to the version that passed R11-R13)
// ============================================================
__global__ void __launch_bounds__(256)
table_gemm(const float* __restrict__ A,
           const float* __restrict__ Wf, const float* __restrict__ Wb,
           const float* __restrict__ b1f, const float* __restrict__ b2f,
           const float* __restrict__ b1b, const float* __restrict__ b2b)
{
    int dir = blockIdx.z;
    const float* W  = dir ? Wb  : Wf;
    const float* b1 = dir ? b1b : b1f;
    const float* b2 = dir ? b2b : b2f;
    float* C = dir ? g_table_b : g_table_f;

    __shared__ __align__(16) float As2[16 * 264];
    __shared__ __align__(16) float Wsm[16 * 132];

    int n0 = blockIdx.x * 128;
    int m0 = blockIdx.y * 128;
    int tid = threadIdx.x;
    int tx = tid & 15;
    int ty = tid >> 4;
    int r  = tid & 127;
    int part = tid >> 7;

    unsigned long long acc[8][4];
#pragma unroll
    for (int i = 0; i < 8; i++)
#pragma unroll
        for (int p = 0; p < 4; p++) acc[i][p] = 0ull;

    for (int k0 = 0; k0 < Ee; k0 += 16) {
        __syncthreads();
        {
            int m = m0 + r;
#pragma unroll
            for (int j = 0; j < 2; j++) {
                int k = k0 + part * 8 + j * 4;
                float4 v = make_float4(0.f, 0.f, 0.f, 0.f);
                if (m < Vv && k + 3 < Ee)
                    v = *(const float4*)&A[(size_t)m * Ee + k];
                int kk = part * 8 + j * 4;
                float* dst0 = &As2[kk * 264 + 2 * r];
                *(float2*)(dst0)           = make_float2(v.x, v.x);
                *(float2*)(dst0 + 264)     = make_float2(v.y, v.y);
                *(float2*)(dst0 + 2 * 264) = make_float2(v.z, v.z);
                *(float2*)(dst0 + 3 * 264) = make_float2(v.w, v.w);
            }
        }
        {
            int n = n0 + r;
#pragma unroll
            for (int j = 0; j < 2; j++) {
                int k = k0 + part * 8 + j * 4;
                float4 v = make_float4(0.f, 0.f, 0.f, 0.f);
                if (n < G4 && k + 3 < Ee)
                    v = *(const float4*)&W[(size_t)n * Ee + k];
                int kk = part * 8 + j * 4;
                Wsm[kk * 132 + r]           = v.x;
                Wsm[(kk + 1) * 132 + r]     = v.y;
                Wsm[(kk + 2) * 132 + r]     = v.z;
                Wsm[(kk + 3) * 132 + r]     = v.w;
            }
        }
        __syncthreads();
#pragma unroll 4
        for (int kk = 0; kk < 16; kk++) {
            const float* arow = &As2[kk * 264 + ty * 16];
            const float* wrow = &Wsm[kk * 132 + tx * 8];
            ulonglong2 a01 = *(const ulonglong2*)(arow);
            ulonglong2 a23 = *(const ulonglong2*)(arow + 4);
            ulonglong2 a45 = *(const ulonglong2*)(arow + 8);
            ulonglong2 a67 = *(const ulonglong2*)(arow + 12);
            ulonglong2 w03 = *(const ulonglong2*)(wrow);
            ulonglong2 w47 = *(const ulonglong2*)(wrow + 4);
            unsigned long long av[8] = {a01.x, a01.y, a23.x, a23.y,
                                        a45.x, a45.y, a67.x, a67.y};
            unsigned long long wv[4] = {w03.x, w03.y, w47.x, w47.y};
#pragma unroll
            for (int i = 0; i < 8; i++)
#pragma unroll
                for (int p = 0; p < 4; p++) fma2(acc[i][p], av[i], wv[p]);
        }
    }

    float bias[8];
#pragma unroll
    for (int j = 0; j < 8; j++) {
        int n = n0 + tx * 8 + j;
        bias[j] = (n < G4) ? (b1[n] + b2[n]) : 0.f;
    }
#pragma unroll
    for (int i = 0; i < 8; i++) {
        int m = m0 + ty * 8 + i;
        if (m >= Vv) continue;
        float vals[8];
#pragma unroll
        for (int p = 0; p < 4; p++) {
            float2 u = u2f(acc[i][p]);
            vals[2 * p]     = u.x + bias[2 * p];
            vals[2 * p + 1] = u.y + bias[2 * p + 1];
        }
        int nb = n0 + tx * 8;
        if (nb + 7 < G4) {
            *(float4*)&C[(size_t)m * G4 + nb]     = make_float4(vals[0], vals[1], vals[2], vals[3]);
            *(float4*)&C[(size_t)m * G4 + nb + 4] = make_float4(vals[4], vals[5], vals[6], vals[7]);
        } else {
#pragma unroll
            for (int j = 0; j < 8; j++)
                if (nb + j < G4) C[(size_t)m * G4 + nb + j] = vals[j];
        }
    }
}

// ============================================================
// Phase 2: one LSTM step, v6 (f32x2 core).
// Block = 10 h (warp-per-h) x 128 b, 320 thr. grid (30,2,2)=120 <=148.
// Per k: 2 LDS.128 broadcast (W dup pairs) + 1 LDS.128 (h: 2 b-pairs)
//        + 8 FFMA2 (16 MAC). Bit-identical accumulation order to v5.
// Smem: Wlo/Whi [10][300][4] = 96KB (staged once/step, conflict-free)
//       + H 2x[100][128] = 100KB ping-pong. 4 syncs/step.
// ============================================================
__global__ void __launch_bounds__(320, 1)
lstm_step(int s, const int* __restrict__ x,
          const float* __restrict__ whhf, const float* __restrict__ whhb)
{
    extern __shared__ __align__(16) float smem[];
    float* Wlo = smem;                 // [10][300][4] = (wi,wi,wf,wf)
    float* Whi = smem + 12000;         // [10][300][4] = (wg,wg,wo,wo)
    float* Hs0 = smem + 24000;         // [100][128]
    float* Hs1 = smem + 24000 + 12800;

    int dir = blockIdx.z;
    const float* whh = dir ? whhb : whhf;
    const float* tbl = dir ? g_table_b : g_table_f;
    float* hseq = dir ? g_hb : g_hf;
    float* cbuf = dir ? g_cb : g_cf;
    int time = dir ? (Sd - 1 - s) : s;

    int h0 = blockIdx.x * 10;
    int b0 = blockIdx.y * 128;
    int tid = threadIdx.x;
    int wid = tid >> 5;              // warp -> h (0..9)
    int lane = tid & 31;             // lane -> 4 b's
    int h = h0 + wid;                // always < 300 (30*10=300)
    int b_lo = b0 + lane * 4;

    // token + table-row prefetch (consumed in epilogue; hidden by staging/GEMM)
    float tv[4][4];
#pragma unroll
    for (int i = 0; i < 4; i++) {
        int t = __ldg(&x[(b_lo + i) * Sd + time]);
        if ((unsigned)t >= (unsigned)Vv) t = 0;
        const float* trow = tbl + (size_t)t * G4 + h;
#pragma unroll
        for (int g = 0; g < 4; g++) tv[i][g] = __ldg(trow + g * Hd);
    }

    // acc[gate][pair]: pair0=(b0,b1), pair1=(b2,b3)
    unsigned long long acc[4][2] = {{0ull,0ull},{0ull,0ull},{0ull,0ull},{0ull,0ull}};

    if (s > 0) {
        int ptime = dir ? (time + 1) : (time - 1);
        const float* hprev = hseq + (size_t)ptime * Hd * Bd;

        // ---- stage W duplicated: thread per (hl,k), 4 gate loads, 2 STS.128
        for (int j = tid; j < 10 * Hd; j += 320) {
            int hl = j / Hd, k = j % Hd;
            int hg = h0 + hl;
            float wi = whh[((size_t)0 * Hd + hg) * Hd + k];
            float wf = whh[((size_t)1 * Hd + hg) * Hd + k];
            float wg = whh[((size_t)2 * Hd + hg) * Hd + k];
            float wo = whh[((size_t)3 * Hd + hg) * Hd + k];
            *(float4*)&Wlo[(size_t)(hl * Hd + k) * 4] = make_float4(wi, wi, wf, wf);
            *(float4*)&Whi[(size_t)(hl * Hd + k) * 4] = make_float4(wg, wg, wo, wo);
        }
        // ---- stage H chunk 0 (rows 0..99)
#pragma unroll
        for (int l = 0; l < 10; l++) {
            int j = tid + l * 320;
            int cc = j >> 5, rr = j & 31;
            *(float4*)&Hs0[cc * 128 + rr * 4] =
                *(const float4*)&hprev[(size_t)cc * Bd + b0 + rr * 4];
        }
        __syncthreads();

        float* bufs[2] = {Hs0, Hs1};
#pragma unroll
        for (int chunk = 0; chunk < 3; chunk++) {
            int cur = chunk & 1;
            if (chunk < 2) {   // prefetch next chunk into other buffer
                const float* hp = hprev + (size_t)((chunk + 1) * 100) * Bd + b0;
                float* dst = bufs[cur ^ 1];
#pragma unroll
                for (int l = 0; l < 10; l++) {
                    int j = tid + l * 320;
                    int cc = j >> 5, rr = j & 31;
                    *(float4*)&dst[cc * 128 + rr * 4] =
                        *(const float4*)&hp[(size_t)cc * Bd + rr * 4];
                }
            }
            const float* wlo = Wlo + (size_t)(wid * Hd + chunk * 100) * 4;
            const float* whi2 = Whi + (size_t)(wid * Hd + chunk * 100) * 4;
            const float* hb  = bufs[cur] + lane * 4;
#pragma unroll 4
            for (int kk = 0; kk < 100; kk++) {
                ulonglong2 wl = *(const ulonglong2*)(wlo + kk * 4);   // (wi,wi),(wf,wf)
                ulonglong2 wh = *(const ulonglong2*)(whi2 + kk * 4);  // (wg,wg),(wo,wo)
                ulonglong2 hv = *(const ulonglong2*)(hb + kk * 128);  // (b0,b1),(b2,b3)
                fma2(acc[0][0], hv.x, wl.x); fma2(acc[0][1], hv.y, wl.x);
                fma2(acc[1][0], hv.x, wl.y); fma2(acc[1][1], hv.y, wl.y);
                fma2(acc[2][0], hv.x, wh.x); fma2(acc[2][1], hv.y, wh.x);
                fma2(acc[3][0], hv.x, wh.y); fma2(acc[3][1], hv.y, wh.y);
            }
            __syncthreads();
        }
    }

    // epilogue: gates -> activations -> h,c  (i = local b 0..3)
    float4 cold4 = make_float4(0.f, 0.f, 0.f, 0.f);
    if (s > 0) cold4 = *(const float4*)&cbuf[(size_t)h * Bd + b_lo];
    float coldA[4] = {cold4.x, cold4.y, cold4.z, cold4.w};
    float hnew[4], cnew[4];
#pragma unroll
    for (int i = 0; i < 4; i++) {
        int p = i >> 1, e = i & 1;
        float2 gi = u2f(acc[0][p]);
        float2 gf = u2f(acc[1][p]);
        float2 gg2 = u2f(acc[2][p]);
        float2 go = u2f(acc[3][p]);
        float ai = clampg((e ? gi.y : gi.x) + tv[i][0]);
        float af = clampg((e ? gf.y : gf.x) + tv[i][1]);
        float ag = clampg((e ? gg2.y : gg2.x) + tv[i][2]);
        float ao = clampg((e ? go.y : go.x) + tv[i][3]);
        float ig = 1.f / (1.f + expf(-ai));
        float fg = 1.f / (1.f + expf(-af));
        float gg = tanhf(ag);
        float og = 1.f / (1.f + expf(-ao));
        float c = fg * coldA[i] + ig * gg;
        cnew[i] = c;
        hnew[i] = og * tanhf(clampg(c));
    }
    *(float4*)&cbuf[(size_t)h * Bd + b_lo] =
        make_float4(cnew[0], cnew[1], cnew[2], cnew[3]);
    *(float4*)&hseq[((size_t)time * Hd + h) * Bd + b_lo] =
        make_float4(hnew[0], hnew[1], hnew[2], hnew[3]);
}

// ============================================================
// Phase 3a: emissions, fp64 accumulation. Block per s, thread per b.
// ============================================================
__global__ void __launch_bounds__(256)
emis_kernel(const float* __restrict__ wproj, const float* __restrict__ bproj)
{
    __shared__ float wp[Td * 2 * Hd];
    int s = blockIdx.x;
    int b = threadIdx.x;
    for (int i = threadIdx.x; i < Td * 2 * Hd; i += blockDim.x) wp[i] = wproj[i];
    __syncthreads();

    const float* f  = g_hf + (size_t)s * Hd * Bd;
    const float* bk = g_hb + (size_t)s * Hd * Bd;
    double acc[Td] = {};
    for (int j = 0; j < Hd; j++) {
        double v = (double)f[(size_t)j * Bd + b];
#pragma unroll
        for (int t = 0; t < Td; t++) acc[t] += v * (double)wp[t * 2 * Hd + j];
    }
    for (int j = 0; j < Hd; j++) {
        double v = (double)bk[(size_t)j * Bd + b];
#pragma unroll
        for (int t = 0; t < Td; t++) acc[t] += v * (double)wp[t * 2 * Hd + Hd + j];
    }
#pragma unroll
    for (int t = 0; t < Td; t++)
        g_em[((size_t)s * Bd + b) * Td + t] = acc[t] + (double)bproj[t];
}

// ============================================================
// Phase 3b: Viterbi DP + backtrack, fp64, float32 tag output.
// ============================================================
__global__ void viterbi_kernel(const float* __restrict__ start_t, const float* __restrict__ end_t,
                               const float* __restrict__ trans, float* __restrict__ out)
{
    __shared__ double tr[Td][Td];
    if (threadIdx.x < Td * Td)
        tr[threadIdx.x / Td][threadIdx.x % Td] = (double)trans[threadIdx.x];
    __syncthreads();
    int b = blockIdx.x * blockDim.x + threadIdx.x;
    if (b >= Bd) return;

    double sc[Td];
#pragma unroll
    for (int t = 0; t < Td; t++)
        sc[t] = (double)start_t[t] + g_em[(size_t)b * Td + t];

    for (int s = 1; s < Sd; s++) {
        const double* em = &g_em[((size_t)s * Bd + b) * Td];
        double ns[Td];
#pragma unroll
        for (int tn = 0; tn < Td; tn++) {
            double best = sc[0] + tr[0][tn];
            int arg = 0;
#pragma unroll
            for (int tp = 1; tp < Td; tp++) {
                double v = sc[tp] + tr[tp][tn];
                if (v > best) { best = v; arg = tp; }
            }
            ns[tn] = best + em[tn];
            g_bp[((size_t)(s - 1) * Bd + b) * Td + tn] = (unsigned char)arg;
        }
#pragma unroll
        for (int t = 0; t < Td; t++) sc[t] = ns[t];
    }

    int last = 0;
    double best = sc[0] + (double)end_t[0];
#pragma unroll
    for (int t = 1; t < Td; t++) {
        double v = sc[t] + (double)end_t[t];
        if (v > best) { best = v; last = t; }
    }
    out[b * Sd + (Sd - 1)] = (float)last;
    int tag = last;
    for (int s = Sd - 2; s >= 0; s--) {
        tag = g_bp[((size_t)s * Bd + b) * Td + tag];
        out[b * Sd + s] = (float)tag;
    }
}

// ============================================================
extern "C" void kernel_launch(void* const* d_in, const int* in_sizes, int n_in,
                              void* d_out, int out_size)
{
    static const int expA[15] = {65536, 9000000, 360000, 360000, 1200, 1200,
                                 360000, 360000, 1200, 1200, 5400, 9, 9, 9, 81};
    bool okA = (n_in == 15), okA4 = (n_in == 15);
    for (int i = 0; i < 15 && n_in == 15; i++) {
        if (in_sizes[i] != expA[i])     okA  = false;
        if (in_sizes[i] != expA[i] * 4) okA4 = false;
    }
    if (!okA && !okA4) {
        SizePack sp; sp.n = n_in;
        for (int i = 0; i < 16; i++) sp.v[i] = (i < n_in) ? in_sizes[i] : -1;
        bad_layout_kernel<<<1, 1>>>(sp);
        return;
    }

    const int*   x       = (const int*)  d_in[0];
    const float* emb     = (const float*)d_in[1];
    const float* wihf    = (const float*)d_in[2];
    const float* whhf    = (const float*)d_in[3];
    const float* bihf    = (const float*)d_in[4];
    const float* bhhf    = (const float*)d_in[5];
    const float* wihb    = (const float*)d_in[6];
    const float* whhb    = (const float*)d_in[7];
    const float* bihb    = (const float*)d_in[8];
    const float* bhhb    = (const float*)d_in[9];
    const float* wproj   = (const float*)d_in[10];
    const float* bproj   = (const float*)d_in[11];
    const float* start_t = (const float*)d_in[12];
    const float* end_t   = (const float*)d_in[13];
    const float* trans   = (const float*)d_in[14];
    float* out = (float*)d_out;

    // Phase 1: vocab gate tables (f32x2)
    dim3 gt((G4 + 127) / 128, (Vv + 127) / 128, 2);
    table_gemm<<<gt, 256>>>(emb, wihf, wihb, bihf, bhhf, bihb, bhhb);

    // Phase 2: 256 per-step launches (f32x2 core, 120 blocks, 320 thr)
    int smem_bytes = (24000 + 2 * 12800) * sizeof(float);   // 198,400 B
    cudaFuncSetAttribute(lstm_step,
                         cudaFuncAttributeMaxDynamicSharedMemorySize, smem_bytes);
    dim3 gs(30, 2, 2);
    for (int s = 0; s < Sd; s++)
        lstm_step<<<gs, 320, smem_bytes>>>(s, x, whhf, whhb);

    // Phase 3
    emis_kernel<<<Sd, Bd>>>(wproj, bproj);
    viterbi_kernel<<<2, 128>>>(start_t, end_t, trans, out);
}

// round 17
// speedup vs baseline: 1.0131x; 1.0131x over previous
#include <cuda_runtime.h>
#include <math.h>
#include <stdio.h>
#include <assert.h>

#define Vv 30000
#define Ee 300
#define Hd 300
#define G4 1200
#define Td 9
#define Bd 256
#define Sd 256

// ---- scratch (device globals) ----
__device__ float  g_table_f[(size_t)Vv * G4];
__device__ float  g_table_b[(size_t)Vv * G4];
__device__ float  g_hf[(size_t)Sd * Hd * Bd];   // [time][h][b]
__device__ float  g_hb[(size_t)Sd * Hd * Bd];
__device__ float  g_cf[Hd * Bd];                // [h][b]
__device__ float  g_cb[Hd * Bd];
__device__ double g_em[(size_t)Sd * Bd * Td];
__device__ unsigned char g_bp[(size_t)(Sd - 1) * Bd * Td];

__device__ __forceinline__ float clampg(float v) {
    return fmaxf(fminf(v, 30.f), -30.f);
}

struct SizePack { int n; int v[16]; };
__global__ void bad_layout_kernel(SizePack sp)
{
    printf("[diag] LAYOUT MISMATCH n_in=%d sizes:", sp.n);
    for (int i = 0; i < 16 && i < sp.n; i++) printf(" %d", sp.v[i]);
    printf("\n");
    assert(0);
}

// ============================================================
// Phase 1: vocab gate table, scalar FFMA, 128x128x16 tile, 8x8 micro.
// (identical to R15's measured version)
// ============================================================
__global__ void __launch_bounds__(256)
table_gemm(const float* __restrict__ A,
           const float* __restrict__ Wf, const float* __restrict__ Wb,
           const float* __restrict__ b1f, const float* __restrict__ b2f,
           const float* __restrict__ b1b, const float* __restrict__ b2b)
{
    int dir = blockIdx.z;
    const float* W  = dir ? Wb  : Wf;
    const float* b1 = dir ? b1b : b1f;
    const float* b2 = dir ? b2b : b2f;
    float* C = dir ? g_table_b : g_table_f;

    __shared__ __align__(16) float As[16 * 132];
    __shared__ __align__(16) float Wsm[16 * 132];

    int n0 = blockIdx.x * 128;
    int m0 = blockIdx.y * 128;
    int tid = threadIdx.x;
    int tx = tid & 15;
    int ty = tid >> 4;
    int r  = tid & 127;
    int part = tid >> 7;

    float acc[8][8] = {};

    for (int k0 = 0; k0 < Ee; k0 += 16) {
        __syncthreads();
        {
            int m = m0 + r;
#pragma unroll
            for (int q = 0; q < 2; q++) {
                int k = k0 + part * 8 + q * 4;
                float4 v = make_float4(0.f, 0.f, 0.f, 0.f);
                if (m < Vv && k + 3 < Ee)
                    v = *(const float4*)&A[(size_t)m * Ee + k];
                int kk = part * 8 + q * 4;
                As[(kk + 0) * 132 + r] = v.x;
                As[(kk + 1) * 132 + r] = v.y;
                As[(kk + 2) * 132 + r] = v.z;
                As[(kk + 3) * 132 + r] = v.w;
            }
        }
        {
            int n = n0 + r;
#pragma unroll
            for (int q = 0; q < 2; q++) {
                int k = k0 + part * 8 + q * 4;
                float4 v = make_float4(0.f, 0.f, 0.f, 0.f);
                if (n < G4 && k + 3 < Ee)
                    v = *(const float4*)&W[(size_t)n * Ee + k];
                int kk = part * 8 + q * 4;
                Wsm[(kk + 0) * 132 + r] = v.x;
                Wsm[(kk + 1) * 132 + r] = v.y;
                Wsm[(kk + 2) * 132 + r] = v.z;
                Wsm[(kk + 3) * 132 + r] = v.w;
            }
        }
        __syncthreads();
#pragma unroll 4
        for (int kk = 0; kk < 16; kk++) {
            float4 a0 = *(const float4*)&As[kk * 132 + ty * 8];
            float4 a1 = *(const float4*)&As[kk * 132 + ty * 8 + 4];
            float4 w0 = *(const float4*)&Wsm[kk * 132 + tx * 8];
            float4 w1 = *(const float4*)&Wsm[kk * 132 + tx * 8 + 4];
            float av[8] = {a0.x, a0.y, a0.z, a0.w, a1.x, a1.y, a1.z, a1.w};
            float wv[8] = {w0.x, w0.y, w0.z, w0.w, w1.x, w1.y, w1.z, w1.w};
#pragma unroll
            for (int i = 0; i < 8; i++)
#pragma unroll
                for (int j = 0; j < 8; j++) acc[i][j] += av[i] * wv[j];
        }
    }

    int nb = n0 + tx * 8;
    float bias[8];
#pragma unroll
    for (int j = 0; j < 8; j++) {
        int n = nb + j;
        bias[j] = (n < G4) ? (b1[n] + b2[n]) : 0.f;
    }
#pragma unroll
    for (int i = 0; i < 8; i++) {
        int m = m0 + ty * 8 + i;
        if (m >= Vv) continue;
        if (nb + 7 < G4) {
            *(float4*)&C[(size_t)m * G4 + nb] =
                make_float4(acc[i][0] + bias[0], acc[i][1] + bias[1],
                            acc[i][2] + bias[2], acc[i][3] + bias[3]);
            *(float4*)&C[(size_t)m * G4 + nb + 4] =
                make_float4(acc[i][4] + bias[4], acc[i][5] + bias[5],
                            acc[i][6] + bias[6], acc[i][7] + bias[7]);
        } else {
#pragma unroll
            for (int j = 0; j < 8; j++)
                if (nb + j < G4) C[(size_t)m * G4 + nb + j] = acc[i][j] + bias[j];
        }
    }
}

// ============================================================
// Phase 2: one LSTM step, v7. Warp-per-h (8 h/block), lane = 1 b.
// Block 8h x 32b, 256 thr; 1200 FFMA/thread, 4 accumulators.
// smem 54.3KB -> 3 blocks/SM (24 warps). grid (38,8,2)=608.
// ============================================================
__global__ void __launch_bounds__(256, 3)
lstm_step(int s, const int* __restrict__ x,
          const float* __restrict__ whhf, const float* __restrict__ whhb)
{
    extern __shared__ __align__(16) float smem[];
    float* Ws  = smem;            // [32 rows (hl*4+g)][304 k]  38,912B
    float* Hs0 = smem + 9728;     // [60][32]                    7,680B
    float* Hs1 = smem + 9728 + 1920;

    int dir = blockIdx.z;
    const float* whh = dir ? whhb : whhf;
    const float* tbl = dir ? g_table_b : g_table_f;
    float* hseq = dir ? g_hb : g_hf;
    float* cbuf = dir ? g_cb : g_cf;
    int time = dir ? (Sd - 1 - s) : s;

    int h0 = blockIdx.x * 8;
    int b0 = blockIdx.y * 32;
    int tid = threadIdx.x;
    int wid = tid >> 5;          // warp -> h
    int lane = tid & 31;         // lane -> b
    int h = h0 + wid;
    int hh = (h < Hd) ? h : (Hd - 1);
    int b = b0 + lane;

    // token + table-row prefetch (consumed in epilogue)
    int t = __ldg(&x[b * Sd + time]);
    if ((unsigned)t >= (unsigned)Vv) t = 0;
    const float* trow = tbl + (size_t)t * G4 + hh;
    float tv[4];
#pragma unroll
    for (int g = 0; g < 4; g++) tv[g] = __ldg(trow + g * Hd);

    float acc[4] = {0.f, 0.f, 0.f, 0.f};

    if (s > 0) {
        int ptime = dir ? (time + 1) : (time - 1);
        const float* hprev = hseq + (size_t)ptime * Hd * Bd + b0;

        // stage whole W tile: Ws[(hl*4+g)*304 + k]
#pragma unroll
        for (int l = 0; l < 10; l++) {
            int j = tid + l * 256;
            if (j < 2400) {
                int rrow = j / 75;          // 0..31 = hl*4+g
                int k4 = j % 75;
                int hl = rrow >> 2, g = rrow & 3;
                if (h0 + hl < Hd) {
                    float4 v = *(const float4*)&whh[((size_t)g * Hd + h0 + hl) * Hd + k4 * 4];
                    *(float4*)&Ws[rrow * 304 + k4 * 4] = v;
                }
            }
        }
        // stage H chunk 0 (60 rows x 32 b = 480 float4)
#pragma unroll
        for (int l = 0; l < 2; l++) {
            int j = tid + l * 256;
            if (j < 480) {
                int cc = j >> 3, rr = j & 7;
                *(float4*)&Hs0[cc * 32 + rr * 4] =
                    *(const float4*)&hprev[(size_t)cc * Bd + rr * 4];
            }
        }

        float* bufs[2] = {Hs0, Hs1};
        int cur = 0;
#pragma unroll
        for (int chunk = 0; chunk < 5; chunk++) {
            __syncthreads();
            if (chunk < 4) {
                const float* hp = hprev + (size_t)((chunk + 1) * 60) * Bd;
                float* dst = bufs[cur ^ 1];
#pragma unroll
                for (int l = 0; l < 2; l++) {
                    int j = tid + l * 256;
                    if (j < 480) {
                        int cc = j >> 3, rr = j & 7;
                        *(float4*)&dst[cc * 32 + rr * 4] =
                            *(const float4*)&hp[(size_t)cc * Bd + rr * 4];
                    }
                }
            }
            const float* wsb = Ws + (wid * 4) * 304 + chunk * 60;
            const float* hb  = bufs[cur] + lane;
#pragma unroll 5
            for (int k4 = 0; k4 < 15; k4++) {
                float4 w0 = *(const float4*)(wsb + k4 * 4);              // gate i
                float4 w1 = *(const float4*)(wsb + 304 + k4 * 4);        // gate f
                float4 w2 = *(const float4*)(wsb + 2 * 304 + k4 * 4);    // gate g
                float4 w3 = *(const float4*)(wsb + 3 * 304 + k4 * 4);    // gate o
                float hv0 = hb[(k4 * 4 + 0) * 32];
                float hv1 = hb[(k4 * 4 + 1) * 32];
                float hv2 = hb[(k4 * 4 + 2) * 32];
                float hv3 = hb[(k4 * 4 + 3) * 32];
                acc[0] += hv0 * w0.x; acc[1] += hv0 * w1.x;
                acc[2] += hv0 * w2.x; acc[3] += hv0 * w3.x;
                acc[0] += hv1 * w0.y; acc[1] += hv1 * w1.y;
                acc[2] += hv1 * w2.y; acc[3] += hv1 * w3.y;
                acc[0] += hv2 * w0.z; acc[1] += hv2 * w1.z;
                acc[2] += hv2 * w2.z; acc[3] += hv2 * w3.z;
                acc[0] += hv3 * w0.w; acc[1] += hv3 * w1.w;
                acc[2] += hv3 * w2.w; acc[3] += hv3 * w3.w;
            }
            cur ^= 1;
        }
    }

    // epilogue
    if (h < Hd) {
        float cold = (s > 0) ? cbuf[(size_t)h * Bd + b] : 0.f;
        float ai = clampg(acc[0] + tv[0]);
        float af = clampg(acc[1] + tv[1]);
        float ag = clampg(acc[2] + tv[2]);
        float ao = clampg(acc[3] + tv[3]);
        float ig = 1.f / (1.f + expf(-ai));
        float fg = 1.f / (1.f + expf(-af));
        float gg = tanhf(ag);
        float og = 1.f / (1.f + expf(-ao));
        float cnew = fg * cold + ig * gg;
        float hnew = og * tanhf(clampg(cnew));
        cbuf[(size_t)h * Bd + b] = cnew;
        hseq[((size_t)time * Hd + h) * Bd + b] = hnew;
    }
}

// ============================================================
// Phase 3a: emissions, fp64 accumulation. Block per s, thread per b.
// ============================================================
__global__ void __launch_bounds__(256)
emis_kernel(const float* __restrict__ wproj, const float* __restrict__ bproj)
{
    __shared__ float wp[Td * 2 * Hd];
    int s = blockIdx.x;
    int b = threadIdx.x;
    for (int i = threadIdx.x; i < Td * 2 * Hd; i += blockDim.x) wp[i] = wproj[i];
    __syncthreads();

    const float* f  = g_hf + (size_t)s * Hd * Bd;
    const float* bk = g_hb + (size_t)s * Hd * Bd;
    double acc[Td] = {};
    for (int j = 0; j < Hd; j++) {
        double v = (double)f[(size_t)j * Bd + b];
#pragma unroll
        for (int t = 0; t < Td; t++) acc[t] += v * (double)wp[t * 2 * Hd + j];
    }
    for (int j = 0; j < Hd; j++) {
        double v = (double)bk[(size_t)j * Bd + b];
#pragma unroll
        for (int t = 0; t < Td; t++) acc[t] += v * (double)wp[t * 2 * Hd + Hd + j];
    }
#pragma unroll
    for (int t = 0; t < Td; t++)
        g_em[((size_t)s * Bd + b) * Td + t] = acc[t] + (double)bproj[t];
}

// ============================================================
// Phase 3b: Viterbi DP + backtrack, fp64, float32 tag output.
// ============================================================
__global__ void viterbi_kernel(const float* __restrict__ start_t, const float* __restrict__ end_t,
                               const float* __restrict__ trans, float* __restrict__ out)
{
    __shared__ double tr[Td][Td];
    if (threadIdx.x < Td * Td)
        tr[threadIdx.x / Td][threadIdx.x % Td] = (double)trans[threadIdx.x];
    __syncthreads();
    int b = blockIdx.x * blockDim.x + threadIdx.x;
    if (b >= Bd) return;

    double sc[Td];
#pragma unroll
    for (int t = 0; t < Td; t++)
        sc[t] = (double)start_t[t] + g_em[(size_t)b * Td + t];

    for (int s = 1; s < Sd; s++) {
        const double* em = &g_em[((size_t)s * Bd + b) * Td];
        double ns[Td];
#pragma unroll
        for (int tn = 0; tn < Td; tn++) {
            double best = sc[0] + tr[0][tn];
            int arg = 0;
#pragma unroll
            for (int tp = 1; tp < Td; tp++) {
                double v = sc[tp] + tr[tp][tn];
                if (v > best) { best = v; arg = tp; }
            }
            ns[tn] = best + em[tn];
            g_bp[((size_t)(s - 1) * Bd + b) * Td + tn] = (unsigned char)arg;
        }
#pragma unroll
        for (int t = 0; t < Td; t++) sc[t] = ns[t];
    }

    int last = 0;
    double best = sc[0] + (double)end_t[0];
#pragma unroll
    for (int t = 1; t < Td; t++) {
        double v = sc[t] + (double)end_t[t];
        if (v > best) { best = v; last = t; }
    }
    out[b * Sd + (Sd - 1)] = (float)last;
    int tag = last;
    for (int s = Sd - 2; s >= 0; s--) {
        tag = g_bp[((size_t)s * Bd + b) * Td + tag];
        out[b * Sd + s] = (float)tag;
    }
}

// ============================================================
extern "C" void kernel_launch(void* const* d_in, const int* in_sizes, int n_in,
                              void* d_out, int out_size)
{
    static const int expA[15] = {65536, 9000000, 360000, 360000, 1200, 1200,
                                 360000, 360000, 1200, 1200, 5400, 9, 9, 9, 81};
    bool okA = (n_in == 15), okA4 = (n_in == 15);
    for (int i = 0; i < 15 && n_in == 15; i++) {
        if (in_sizes[i] != expA[i])     okA  = false;
        if (in_sizes[i] != expA[i] * 4) okA4 = false;
    }
    if (!okA && !okA4) {
        SizePack sp; sp.n = n_in;
        for (int i = 0; i < 16; i++) sp.v[i] = (i < n_in) ? in_sizes[i] : -1;
        bad_layout_kernel<<<1, 1>>>(sp);
        return;
    }

    const int*   x       = (const int*)  d_in[0];
    const float* emb     = (const float*)d_in[1];
    const float* wihf    = (const float*)d_in[2];
    const float* whhf    = (const float*)d_in[3];
    const float* bihf    = (const float*)d_in[4];
    const float* bhhf    = (const float*)d_in[5];
    const float* wihb    = (const float*)d_in[6];
    const float* whhb    = (const float*)d_in[7];
    const float* bihb    = (const float*)d_in[8];
    const float* bhhb    = (const float*)d_in[9];
    const float* wproj   = (const float*)d_in[10];
    const float* bproj   = (const float*)d_in[11];
    const float* start_t = (const float*)d_in[12];
    const float* end_t   = (const float*)d_in[13];
    const float* trans   = (const float*)d_in[14];
    float* out = (float*)d_out;

    // Phase 1: vocab gate tables (scalar)
    dim3 gt((G4 + 127) / 128, (Vv + 127) / 128, 2);
    table_gemm<<<gt, 256>>>(emb, wihf, wihb, bihf, bhhf, bihb, bhhb);

    // Phase 2: 256 per-step launches, v7 (608 blocks, 3/SM)
    int smem_bytes = (9728 + 2 * 1920) * sizeof(float);   // 54,272 B
    cudaFuncSetAttribute(lstm_step,
                         cudaFuncAttributeMaxDynamicSharedMemorySize, smem_bytes);
    dim3 gs(38, 8, 2);
    for (int s = 0; s < Sd; s++)
        lstm_step<<<gs, 256, smem_bytes>>>(s, x, whhf, whhb);

    // Phase 3
    emis_kernel<<<Sd, Bd>>>(wproj, bproj);
    viterbi_kernel<<<2, 128>>>(start_t, end_t, trans, out);
}